// round 15
// baseline (speedup 1.0000x reference)
#include <cuda_runtime.h>
#include <cuda_fp16.h>
#include <cstdint>

// out[m][d] = sum_k ecg[m*128+k] * W[d*128+k] + b[d],  M=196608, K=128, N=64.
// 2-term fp16 HMMA: D = A16*Whi + A16*Wlo (fp32 accum), rel_err ~2e-4.
// R15 = R14 + W stored as ldsm-native 512B fragment blocks:
//   block(s,ntp,t) holds the exact 4x(8x8) b16 matrices one ldmatrix.x4 reads,
//   lane l at byte 16*l -> each ldsm touches 4 contiguous 128B lines (4 L1
//   wavefronts, conflict-free) instead of ~16-32 with the padded-row layout.

#define THREADS 128
#define BM 128
#define W_BYTES 32768    // 8 s x 4 ntp x 2 (hi/lo) x 512B
#define STG_STRIDE 72    // epilogue staging row stride in floats (conflict-free)

__device__ __forceinline__ uint32_t s2u(const void* p) {
    uint32_t a;
    asm("{ .reg .u64 t; cvta.to.shared.u64 t, %1; cvt.u32.u64 %0, t; }" : "=r"(a) : "l"(p));
    return a;
}

__device__ __forceinline__ uint32_t f16x2(float x, float y) {
    uint32_t r;
    asm("cvt.rn.f16x2.f32 %0, %1, %2;" : "=r"(r) : "f"(y), "f"(x));
    return r;
}

__device__ __forceinline__ void split2h(float x, float y, uint32_t& hi, uint32_t& lo) {
    hi = f16x2(x, y);
    __half2 h = *reinterpret_cast<__half2*>(&hi);
    float2 hf = __half22float2(h);
    lo = f16x2(x - hf.x, y - hf.y);
}

__device__ __forceinline__ void ldsm4(uint32_t* r, uint32_t addr) {
    asm volatile("ldmatrix.sync.aligned.m8n8.x4.shared.b16 {%0,%1,%2,%3}, [%4];"
                 : "=r"(r[0]), "=r"(r[1]), "=r"(r[2]), "=r"(r[3]) : "r"(addr));
}

__device__ __forceinline__ void mma16816h(float* c,
                                          uint32_t a0, uint32_t a1, uint32_t a2, uint32_t a3,
                                          uint32_t b0, uint32_t b1) {
    asm volatile(
        "mma.sync.aligned.m16n8k16.row.col.f32.f16.f16.f32 "
        "{%0,%1,%2,%3}, {%4,%5,%6,%7}, {%8,%9}, {%0,%1,%2,%3};"
        : "+f"(c[0]), "+f"(c[1]), "+f"(c[2]), "+f"(c[3])
        : "r"(a0), "r"(a1), "r"(a2), "r"(a3), "r"(b0), "r"(b1));
}

__global__ __launch_bounds__(THREADS, 4)
void ecg_tok_mma(const float* __restrict__ ecg,
                 const float* __restrict__ W,
                 const float* __restrict__ bias,
                 float* __restrict__ out,
                 long long xelems, int fillCount) {
    // W fragment blocks; reused as epilogue staging buffer after a sync.
    __shared__ __align__(16) char smem_raw[W_BYTES];

    const int tid  = threadIdx.x;
    const int warp = tid >> 5;
    const int lane = tid & 31;
    const long long m0 = (long long)blockIdx.x * BM;
    const uint32_t sb = s2u(smem_raw);

    // ---- folded fill: beat_intervals tail ----
    {
        int fi = blockIdx.x * THREADS + tid;
        if (fi < fillCount) out[xelems + fi] = 128.0f;
    }

    // ---- prologue: load + split W into ldsm-native 512B blocks ----
    // Per-16-chunk column perm: global pair g -> slice pair p = (g>>1)+(g&1)*4
    // (same perm applied to A fragments, so the GEMM result is unchanged).
    // Block (chunk, ntp, t): lane l holds 16B at byte 16*l; lane =
    //   (nn<8 ? 0:16) + (khalf ? 8:0) + (nn&7),  nn = n&15, khalf = p>>2.
    #pragma unroll
    for (int it = 0; it < 16; it++) {
        int idx   = tid + it * THREADS;     // 0..2047
        int n     = idx >> 5;
        int r     = idx & 31;
        int chunk = r >> 2;
        int q     = r & 3;                  // global pairs 2q (p=q), 2q+1 (p=q+4)
        float4 v = *reinterpret_cast<const float4*>(W + n * 128 + chunk * 16 + q * 4);
        uint32_t h0, l0, h1, l1;
        split2h(v.x, v.y, h0, l0);          // pair 2q   -> khalf 0
        split2h(v.z, v.w, h1, l1);          // pair 2q+1 -> khalf 1
        int nn    = n & 15;
        int lane0 = ((nn & 8) << 1) + (nn & 7);       // khalf 0 lane
        uint32_t blk = (uint32_t)((chunk * 4 + (n >> 4)) * 1024);  // hi block
        *reinterpret_cast<uint32_t*>(smem_raw + blk + lane0 * 16 + q * 4)        = h0;
        *reinterpret_cast<uint32_t*>(smem_raw + blk + (lane0 + 8) * 16 + q * 4)  = h1;
        *reinterpret_cast<uint32_t*>(smem_raw + blk + 512 + lane0 * 16 + q * 4)       = l0;
        *reinterpret_cast<uint32_t*>(smem_raw + blk + 512 + (lane0 + 8) * 16 + q * 4) = l1;
    }
    __syncthreads();

    // ldsm address: block base + 16*lane  (contiguous 512B per ldsm)
    const uint32_t lm_base = sb + (uint32_t)(lane * 16);

    // A geometry: warp rows = warp*32 + {0..31}; lane float4 at col 4*(lane&3)
    const int arow = warp * 32 + (lane >> 2);
    const float* abase = ecg + (m0 + arow) * 128 + 4 * (lane & 3);

    float acc[2][8][4];
    #pragma unroll
    for (int f = 0; f < 2; f++)
        #pragma unroll
        for (int nt = 0; nt < 8; nt++)
            #pragma unroll
            for (int j = 0; j < 4; j++) acc[f][nt][j] = 0.0f;

    // A prefetch (1-deep)
    float4 cur[4];
    #pragma unroll
    for (int j = 0; j < 4; j++)
        cur[j] = *reinterpret_cast<const float4*>(abase + j * 8 * 128);

    #pragma unroll
    for (int s = 0; s < 8; s++) {
        // convert current A chunk to fp16 fragments
        uint32_t ah[8];
        #pragma unroll
        for (int j = 0; j < 4; j++) {
            ah[2 * j]     = f16x2(cur[j].x, cur[j].y);
            ah[2 * j + 1] = f16x2(cur[j].z, cur[j].w);
        }

        // prefetch next A chunk
        if (s < 7) {
            #pragma unroll
            for (int j = 0; j < 4; j++)
                cur[j] = *reinterpret_cast<const float4*>(
                    abase + (s + 1) * 16 + j * 8 * 128);
        }

        #pragma unroll
        for (int ntp = 0; ntp < 4; ntp++) {
            const uint32_t blk = (uint32_t)((s * 4 + ntp) * 1024);
            uint32_t bh[4], bl[4];
            ldsm4(bh, lm_base + blk);          // hi block
            ldsm4(bl, lm_base + blk + 512);    // lo block

            float* c00 = acc[0][2 * ntp];
            float* c01 = acc[0][2 * ntp + 1];
            float* c10 = acc[1][2 * ntp];
            float* c11 = acc[1][2 * ntp + 1];

            // term 1: A16 * Whi   (term-major: same-acc RAW distance 4)
            mma16816h(c00, ah[0], ah[2], ah[1], ah[3], bh[0], bh[1]);
            mma16816h(c01, ah[0], ah[2], ah[1], ah[3], bh[2], bh[3]);
            mma16816h(c10, ah[4], ah[6], ah[5], ah[7], bh[0], bh[1]);
            mma16816h(c11, ah[4], ah[6], ah[5], ah[7], bh[2], bh[3]);
            // term 2: A16 * Wlo
            mma16816h(c00, ah[0], ah[2], ah[1], ah[3], bl[0], bl[1]);
            mma16816h(c01, ah[0], ah[2], ah[1], ah[3], bl[2], bl[3]);
            mma16816h(c10, ah[4], ah[6], ah[5], ah[7], bl[0], bl[1]);
            mma16816h(c11, ah[4], ah[6], ah[5], ah[7], bl[2], bl[3]);
        }
    }

    // ---- epilogue: stage per-warp in smem (reuses W region), coalesced STG ----
    __syncthreads();   // all warps done reading W smem

    float* stage = reinterpret_cast<float*>(smem_raw) + warp * (16 * STG_STRIDE);
    const float4 bv4 = reinterpret_cast<const float4*>(bias)[lane & 15];
    const int r0 = lane >> 2;        // 0..7
    const int c0 = 2 * (lane & 3);   // 0,2,4,6
    const int rr = lane >> 4;        // 0/1
    const int cc = lane & 15;        // float4 col index

    #pragma unroll
    for (int f = 0; f < 2; f++) {
        __syncwarp();
        #pragma unroll
        for (int nt = 0; nt < 8; nt++) {
            *reinterpret_cast<float2*>(&stage[STG_STRIDE * r0 + 8 * nt + c0]) =
                make_float2(acc[f][nt][0], acc[f][nt][1]);
            *reinterpret_cast<float2*>(&stage[STG_STRIDE * (r0 + 8) + 8 * nt + c0]) =
                make_float2(acc[f][nt][2], acc[f][nt][3]);
        }
        __syncwarp();

        const long long rowbase = m0 + warp * 32 + f * 16;
        #pragma unroll
        for (int i = 0; i < 8; i++) {
            int r = 2 * i + rr;
            float4 v = *reinterpret_cast<float4*>(&stage[STG_STRIDE * r + 4 * cc]);
            v.x += bv4.x; v.y += bv4.y; v.z += bv4.z; v.w += bv4.w;
            *reinterpret_cast<float4*>(out + (rowbase + r) * 64 + 4 * cc) = v;
        }
    }
}

extern "C" void kernel_launch(void* const* d_in, const int* in_sizes, int n_in,
                              void* d_out, int out_size) {
    const float* ecg = (const float*)d_in[0];
    const float* W   = (const float*)d_in[1];
    const float* b   = (const float*)d_in[2];
    float* out = (float*)d_out;

    const int M = in_sizes[0] / 128;
    const long long xelems = (long long)M * 64;
    const int fillCount = out_size - (int)xelems;

    ecg_tok_mma<<<M / BM, THREADS>>>(ecg, W, b, out, xelems, fillCount);
}

// round 16
// speedup vs baseline: 1.2967x; 1.2967x over previous
#include <cuda_runtime.h>
#include <cuda_fp16.h>
#include <cstdint>

// out[m][d] = sum_k ecg[m*128+k] * W[d*128+k] + b[d],  M=196608, K=128, N=64.
// 1-term fp16 HMMA: D = A16 * W16 (fp32 accum). rel_err ~3e-4 (< 1e-3 gate).
// R16 = R14 structure with single-precision-level W (no hi/lo split):
// halves ldsm traffic, MMA count, W prologue and W smem.

#define THREADS 128
#define BM 128
#define WPAD 136         // fp16 per padded W row (272 B -> conflict-free ldmatrix)
#define SMEM_BYTES 18432 // max(W region 17408 B, staging 4*16*72*4 = 18432 B)
#define STG_STRIDE 72    // epilogue staging row stride in floats (conflict-free)

__device__ __forceinline__ uint32_t s2u(const void* p) {
    uint32_t a;
    asm("{ .reg .u64 t; cvta.to.shared.u64 t, %1; cvt.u32.u64 %0, t; }" : "=r"(a) : "l"(p));
    return a;
}

__device__ __forceinline__ uint32_t f16x2(float x, float y) {
    uint32_t r;
    asm("cvt.rn.f16x2.f32 %0, %1, %2;" : "=r"(r) : "f"(y), "f"(x));
    return r;
}

__device__ __forceinline__ void ldsm4(uint32_t* r, uint32_t addr) {
    asm volatile("ldmatrix.sync.aligned.m8n8.x4.shared.b16 {%0,%1,%2,%3}, [%4];"
                 : "=r"(r[0]), "=r"(r[1]), "=r"(r[2]), "=r"(r[3]) : "r"(addr));
}

__device__ __forceinline__ void mma16816h(float* c,
                                          uint32_t a0, uint32_t a1, uint32_t a2, uint32_t a3,
                                          uint32_t b0, uint32_t b1) {
    asm volatile(
        "mma.sync.aligned.m16n8k16.row.col.f32.f16.f16.f32 "
        "{%0,%1,%2,%3}, {%4,%5,%6,%7}, {%8,%9}, {%0,%1,%2,%3};"
        : "+f"(c[0]), "+f"(c[1]), "+f"(c[2]), "+f"(c[3])
        : "r"(a0), "r"(a1), "r"(a2), "r"(a3), "r"(b0), "r"(b1));
}

__global__ __launch_bounds__(THREADS, 4)
void ecg_tok_mma(const float* __restrict__ ecg,
                 const float* __restrict__ W,
                 const float* __restrict__ bias,
                 float* __restrict__ out,
                 long long xelems, int fillCount) {
    // W16 tile (17408 B); reused as epilogue staging buffer after a sync.
    __shared__ __align__(16) char smem_raw[SMEM_BYTES];
    uint32_t* W32 = reinterpret_cast<uint32_t*>(smem_raw);

    const int tid  = threadIdx.x;
    const int warp = tid >> 5;
    const int lane = tid & 31;
    const long long m0 = (long long)blockIdx.x * BM;

    // ---- folded fill: beat_intervals tail ----
    {
        int fi = blockIdx.x * THREADS + tid;
        if (fi < fillCount) out[xelems + fi] = 128.0f;
    }

    // ---- prologue: load + convert W to fp16 with per-16-chunk column perm ----
    // global pair g of a chunk -> slice pair (g>>1) + (g&1)*4 (same perm on A).
    #pragma unroll
    for (int it = 0; it < 16; it++) {
        int idx   = tid + it * THREADS;     // 0..2047
        int n     = idx >> 5;
        int r     = idx & 31;
        int chunk = r >> 2;
        int q     = r & 3;
        float4 v = *reinterpret_cast<const float4*>(W + n * 128 + chunk * 16 + q * 4);
        uint32_t h0 = f16x2(v.x, v.y);      // pair 2q   -> slice pair q
        uint32_t h1 = f16x2(v.z, v.w);      // pair 2q+1 -> slice pair q+4
        int u = n * (WPAD / 2) + chunk * 8 + q;
        W32[u]     = h0;
        W32[u + 4] = h1;
    }
    __syncthreads();

    // ldmatrix lane addressing
    const int lm_row  = ((lane >> 4) << 3) + (lane & 7);
    const int lm_kofs = ((lane >> 3) & 1) << 4;   // bytes
    const uint32_t w_base = s2u(W32) + (uint32_t)(lm_row * (WPAD * 2) + lm_kofs);

    // A geometry: warp rows = warp*32 + {0..31}; lane float4 at col 4*(lane&3)
    const int arow = warp * 32 + (lane >> 2);
    const float* abase = ecg + (m0 + arow) * 128 + 4 * (lane & 3);

    float acc[2][8][4];
    #pragma unroll
    for (int f = 0; f < 2; f++)
        #pragma unroll
        for (int nt = 0; nt < 8; nt++)
            #pragma unroll
            for (int j = 0; j < 4; j++) acc[f][nt][j] = 0.0f;

    // A prefetch (1-deep)
    float4 cur[4];
    #pragma unroll
    for (int j = 0; j < 4; j++)
        cur[j] = *reinterpret_cast<const float4*>(abase + j * 8 * 128);

    #pragma unroll
    for (int s = 0; s < 8; s++) {
        // convert current A chunk to fp16 fragments
        uint32_t ah[8];
        #pragma unroll
        for (int j = 0; j < 4; j++) {
            ah[2 * j]     = f16x2(cur[j].x, cur[j].y);
            ah[2 * j + 1] = f16x2(cur[j].z, cur[j].w);
        }

        // prefetch next A chunk
        if (s < 7) {
            #pragma unroll
            for (int j = 0; j < 4; j++)
                cur[j] = *reinterpret_cast<const float4*>(
                    abase + (s + 1) * 16 + j * 8 * 128);
        }

        #pragma unroll
        for (int ntp = 0; ntp < 4; ntp++) {
            const uint32_t off = (uint32_t)(ntp * 16 * WPAD * 2 + s * 32);
            uint32_t bh[4];
            ldsm4(bh, w_base + off);

            // frag f: a0=ah[4f], a1=ah[4f+2], a2=ah[4f+1], a3=ah[4f+3]
            // issue order c00,c01,c10,c11 -> same-acc RAW distance 4
            mma16816h(acc[0][2 * ntp],     ah[0], ah[2], ah[1], ah[3], bh[0], bh[1]);
            mma16816h(acc[0][2 * ntp + 1], ah[0], ah[2], ah[1], ah[3], bh[2], bh[3]);
            mma16816h(acc[1][2 * ntp],     ah[4], ah[6], ah[5], ah[7], bh[0], bh[1]);
            mma16816h(acc[1][2 * ntp + 1], ah[4], ah[6], ah[5], ah[7], bh[2], bh[3]);
        }
    }

    // ---- epilogue: stage per-warp in smem (reuses W region), coalesced STG ----
    __syncthreads();   // all warps done reading W smem

    float* stage = reinterpret_cast<float*>(smem_raw) + warp * (16 * STG_STRIDE);
    const float4 bv4 = reinterpret_cast<const float4*>(bias)[lane & 15];
    const int r0 = lane >> 2;        // 0..7
    const int c0 = 2 * (lane & 3);   // 0,2,4,6
    const int rr = lane >> 4;        // 0/1
    const int cc = lane & 15;        // float4 col index

    #pragma unroll
    for (int f = 0; f < 2; f++) {
        __syncwarp();
        #pragma unroll
        for (int nt = 0; nt < 8; nt++) {
            *reinterpret_cast<float2*>(&stage[STG_STRIDE * r0 + 8 * nt + c0]) =
                make_float2(acc[f][nt][0], acc[f][nt][1]);
            *reinterpret_cast<float2*>(&stage[STG_STRIDE * (r0 + 8) + 8 * nt + c0]) =
                make_float2(acc[f][nt][2], acc[f][nt][3]);
        }
        __syncwarp();

        const long long rowbase = m0 + warp * 32 + f * 16;
        #pragma unroll
        for (int i = 0; i < 8; i++) {
            int r = 2 * i + rr;
            float4 v = *reinterpret_cast<float4*>(&stage[STG_STRIDE * r + 4 * cc]);
            v.x += bv4.x; v.y += bv4.y; v.z += bv4.z; v.w += bv4.w;
            *reinterpret_cast<float4*>(out + (rowbase + r) * 64 + 4 * cc) = v;
        }
    }
}

extern "C" void kernel_launch(void* const* d_in, const int* in_sizes, int n_in,
                              void* d_out, int out_size) {
    const float* ecg = (const float*)d_in[0];
    const float* W   = (const float*)d_in[1];
    const float* b   = (const float*)d_in[2];
    float* out = (float*)d_out;

    const int M = in_sizes[0] / 128;
    const long long xelems = (long long)M * 64;
    const int fillCount = out_size - (int)xelems;

    ecg_tok_mma<<<M / BM, THREADS>>>(ecg, W, b, out, xelems, fillCount);
}

// round 17
// speedup vs baseline: 1.3791x; 1.0635x over previous
#include <cuda_runtime.h>
#include <cuda_fp16.h>
#include <cstdint>

// out[m][d] = sum_k ecg[m*128+k] * W[d*128+k] + b[d],  M=196608, K=128, N=64.
// 1-term fp16 HMMA: D = A16 * W16 (fp32 accum), rel_err ~3e-4.
// R17 = R16 + full-tile A staging via cp.async: all 8 k-chunk groups (64 KB)
// issued before the mainloop -> ~4x in-flight DRAM bytes per SM. Self-produced
// lane mapping keeps the mainloop barrier-free (per-thread wait_group).

#define THREADS 128
#define BM 128
#define WPAD 136           // fp16 per padded W row (272 B rows)
#define W_BYTES 17408      // 64 * WPAD * 2
#define A_OFF W_BYTES      // A staging region follows W
#define CHUNKB 8192        // one k-chunk: 128 rows x 64 B
#define SMEM_TOTAL (W_BYTES + 8 * CHUNKB)   // 82944 B
#define STG_STRIDE 72      // epilogue staging row stride (floats); reuses A region

__device__ __forceinline__ uint32_t s2u(const void* p) {
    uint32_t a;
    asm("{ .reg .u64 t; cvta.to.shared.u64 t, %1; cvt.u32.u64 %0, t; }" : "=r"(a) : "l"(p));
    return a;
}

__device__ __forceinline__ uint32_t f16x2(float x, float y) {
    uint32_t r;
    asm("cvt.rn.f16x2.f32 %0, %1, %2;" : "=r"(r) : "f"(y), "f"(x));
    return r;
}

__device__ __forceinline__ void ldsm4(uint32_t* r, uint32_t addr) {
    asm volatile("ldmatrix.sync.aligned.m8n8.x4.shared.b16 {%0,%1,%2,%3}, [%4];"
                 : "=r"(r[0]), "=r"(r[1]), "=r"(r[2]), "=r"(r[3]) : "r"(addr));
}

__device__ __forceinline__ void mma16816h(float* c,
                                          uint32_t a0, uint32_t a1, uint32_t a2, uint32_t a3,
                                          uint32_t b0, uint32_t b1) {
    asm volatile(
        "mma.sync.aligned.m16n8k16.row.col.f32.f16.f16.f32 "
        "{%0,%1,%2,%3}, {%4,%5,%6,%7}, {%8,%9}, {%0,%1,%2,%3};"
        : "+f"(c[0]), "+f"(c[1]), "+f"(c[2]), "+f"(c[3])
        : "r"(a0), "r"(a1), "r"(a2), "r"(a3), "r"(b0), "r"(b1));
}

__device__ __forceinline__ void cpa16(uint32_t dst, const float* src) {
    asm volatile("cp.async.cg.shared.global [%0], [%1], 16;" :: "r"(dst), "l"(src));
}
__device__ __forceinline__ void cpa_commit() {
    asm volatile("cp.async.commit_group;" ::: "memory");
}
template <int N>
__device__ __forceinline__ void cpa_wait() {
    asm volatile("cp.async.wait_group %0;" :: "n"(N) : "memory");
}

__global__ __launch_bounds__(THREADS, 2)
void ecg_tok_mma(const float* __restrict__ ecg,
                 const float* __restrict__ W,
                 const float* __restrict__ bias,
                 float* __restrict__ out,
                 long long xelems, int fillCount) {
    extern __shared__ __align__(16) char smem[];
    uint32_t* W32 = reinterpret_cast<uint32_t*>(smem);
    const uint32_t sb = s2u(smem);

    const int tid  = threadIdx.x;
    const int warp = tid >> 5;
    const int lane = tid & 31;
    const long long m0 = (long long)blockIdx.x * BM;

    // ---- A staging: issue ALL 8 k-chunk groups up front (64 KB in flight) ----
    // Chunk s layout: [row 0..127][64 B]; lane l of warp w writes bytes 16*l of
    // rows w*32 + (l>>2) + 8j  ->  dst = s*CHUNKB + w*2048 + j*512 + l*16.
    // Consumer (same lane) reads exactly those bytes: self-produced, so
    // per-thread cp.async.wait_group orders the mainloop with no barriers.
    {
        const uint32_t dst0 = sb + A_OFF + (uint32_t)(warp * 2048 + lane * 16);
        const float* src0 = ecg + (m0 + warp * 32 + (lane >> 2)) * 128 + (lane & 3) * 4;
        #pragma unroll
        for (int s = 0; s < 8; s++) {
            #pragma unroll
            for (int j = 0; j < 4; j++)
                cpa16(dst0 + (uint32_t)(s * CHUNKB + j * 512),
                      src0 + s * 16 + j * 8 * 128);
            cpa_commit();
        }
    }

    // ---- folded fill: beat_intervals tail ----
    {
        int fi = blockIdx.x * THREADS + tid;
        if (fi < fillCount) out[xelems + fi] = 128.0f;
    }

    // ---- W prologue: load + convert to fp16 with per-16-chunk column perm ----
    // global pair g of a chunk -> slice pair (g>>1) + (g&1)*4 (same perm on A).
    #pragma unroll
    for (int it = 0; it < 16; it++) {
        int idx   = tid + it * THREADS;     // 0..2047
        int n     = idx >> 5;
        int r     = idx & 31;
        int chunk = r >> 2;
        int q     = r & 3;
        float4 v = *reinterpret_cast<const float4*>(W + n * 128 + chunk * 16 + q * 4);
        int u = n * (WPAD / 2) + chunk * 8 + q;
        W32[u]     = f16x2(v.x, v.y);
        W32[u + 4] = f16x2(v.z, v.w);
    }
    __syncthreads();

    // ldmatrix lane addressing
    const int lm_row  = ((lane >> 4) << 3) + (lane & 7);
    const int lm_kofs = ((lane >> 3) & 1) << 4;   // bytes
    const uint32_t w_base = sb + (uint32_t)(lm_row * (WPAD * 2) + lm_kofs);

    // A consumer base: byte 16*lane within (chunk, warp) block
    const uint32_t a_base = sb + A_OFF + (uint32_t)(warp * 2048 + lane * 16);

    float acc[2][8][4];
    #pragma unroll
    for (int f = 0; f < 2; f++)
        #pragma unroll
        for (int nt = 0; nt < 8; nt++)
            #pragma unroll
            for (int j = 0; j < 4; j++) acc[f][nt][j] = 0.0f;

    #pragma unroll
    for (int s = 0; s < 8; s++) {
        // wait for chunk s (groups issued: 8; allow 7-s still pending)
        switch (s) {
            case 0: cpa_wait<7>(); break;
            case 1: cpa_wait<6>(); break;
            case 2: cpa_wait<5>(); break;
            case 3: cpa_wait<4>(); break;
            case 4: cpa_wait<3>(); break;
            case 5: cpa_wait<2>(); break;
            case 6: cpa_wait<1>(); break;
            default: cpa_wait<0>(); break;
        }

        // load A chunk from smem (4 LDS.128, contiguous 512B/warp-op) + convert
        uint32_t ah[8];
        #pragma unroll
        for (int j = 0; j < 4; j++) {
            float4 v = *reinterpret_cast<const float4*>(
                smem + (a_base - sb) + s * CHUNKB + j * 512);
            ah[2 * j]     = f16x2(v.x, v.y);
            ah[2 * j + 1] = f16x2(v.z, v.w);
        }

        #pragma unroll
        for (int ntp = 0; ntp < 4; ntp++) {
            const uint32_t off = (uint32_t)(ntp * 16 * WPAD * 2 + s * 32);
            uint32_t bh[4];
            ldsm4(bh, w_base + off);

            // frag f: a0=ah[4f], a1=ah[4f+2], a2=ah[4f+1], a3=ah[4f+3]
            mma16816h(acc[0][2 * ntp],     ah[0], ah[2], ah[1], ah[3], bh[0], bh[1]);
            mma16816h(acc[0][2 * ntp + 1], ah[0], ah[2], ah[1], ah[3], bh[2], bh[3]);
            mma16816h(acc[1][2 * ntp],     ah[4], ah[6], ah[5], ah[7], bh[0], bh[1]);
            mma16816h(acc[1][2 * ntp + 1], ah[4], ah[6], ah[5], ah[7], bh[2], bh[3]);
        }
    }

    // ---- epilogue: stage per-warp in smem (reuses A region), coalesced STG ----
    __syncthreads();   // all warps done with their A chunks (regions disjoint,
                       // but cheap and keeps the staging reuse safe)

    float* stage = reinterpret_cast<float*>(smem + A_OFF) + warp * (16 * STG_STRIDE);
    const float4 bv4 = reinterpret_cast<const float4*>(bias)[lane & 15];
    const int r0 = lane >> 2;        // 0..7
    const int c0 = 2 * (lane & 3);   // 0,2,4,6
    const int rr = lane >> 4;        // 0/1
    const int cc = lane & 15;        // float4 col index

    #pragma unroll
    for (int f = 0; f < 2; f++) {
        __syncwarp();
        #pragma unroll
        for (int nt = 0; nt < 8; nt++) {
            *reinterpret_cast<float2*>(&stage[STG_STRIDE * r0 + 8 * nt + c0]) =
                make_float2(acc[f][nt][0], acc[f][nt][1]);
            *reinterpret_cast<float2*>(&stage[STG_STRIDE * (r0 + 8) + 8 * nt + c0]) =
                make_float2(acc[f][nt][2], acc[f][nt][3]);
        }
        __syncwarp();

        const long long rowbase = m0 + warp * 32 + f * 16;
        #pragma unroll
        for (int i = 0; i < 8; i++) {
            int r = 2 * i + rr;
            float4 v = *reinterpret_cast<float4*>(&stage[STG_STRIDE * r + 4 * cc]);
            v.x += bv4.x; v.y += bv4.y; v.z += bv4.z; v.w += bv4.w;
            *reinterpret_cast<float4*>(out + (rowbase + r) * 64 + 4 * cc) = v;
        }
    }
}

extern "C" void kernel_launch(void* const* d_in, const int* in_sizes, int n_in,
                              void* d_out, int out_size) {
    const float* ecg = (const float*)d_in[0];
    const float* W   = (const float*)d_in[1];
    const float* b   = (const float*)d_in[2];
    float* out = (float*)d_out;

    const int M = in_sizes[0] / 128;
    const long long xelems = (long long)M * 64;
    const int fillCount = out_size - (int)xelems;

    cudaFuncSetAttribute(ecg_tok_mma, cudaFuncAttributeMaxDynamicSharedMemorySize,
                         SMEM_TOTAL);
    ecg_tok_mma<<<M / BM, THREADS, SMEM_TOTAL>>>(ecg, W, b, out, xelems, fillCount);
}